// round 9
// baseline (speedup 1.0000x reference)
#include <cuda_runtime.h>
#include <cstdint>

// Problem constants
#define T_LEN 256
#define S_N   32
#define C_IN  32
#define A_N   128
#define H_DIR 64
#define G4    256      // 4*H_DIR gate rows
#define NB    32       // sequences (assets) per CTA
#define ZROWS 96       // C_IN + H_DIR rows of the per-step operand tile

// Shared memory layout (in floats)
#define WSM_SZ (96 * 256)          // transposed weights: wsm[c*256 + j]
#define GSM_STRIDE 33              // padded row stride for gate exchange
#define GSM_SZ (256 * GSM_STRIDE)  // gsm[j*33 + nb]
#define ZSM_SZ (96 * 32)           // zsm[row*32 + nb]; rows 0..31 = x_t, 32..95 = h
#define GSM_OFF WSM_SZ
#define ZSM_OFF (WSM_SZ + GSM_SZ)
#define SMEM_FLOATS (WSM_SZ + GSM_SZ + ZSM_SZ)
#define SMEM_BYTES (SMEM_FLOATS * 4)

// ---- packed fp32x2 helpers (Blackwell FFMA2: only reachable via PTX) ----
__device__ __forceinline__ unsigned long long pack2(float w) {
    unsigned long long r;
    unsigned int u = __float_as_uint(w);
    asm("mov.b64 %0, {%1, %1};" : "=l"(r) : "r"(u));
    return r;
}
__device__ __forceinline__ void fma2(unsigned long long& d,
                                     unsigned long long a,
                                     unsigned long long b) {
    asm("fma.rn.f32x2 %0, %1, %2, %0;" : "+l"(d) : "l"(a), "l"(b));
}
__device__ __forceinline__ float2 unpack2(unsigned long long v) {
    unsigned int lo, hi;
    asm("mov.b64 {%0, %1}, %2;" : "=r"(lo), "=r"(hi) : "l"(v));
    return make_float2(__uint_as_float(lo), __uint_as_float(hi));
}

// Fast, accurate-enough nonlinearities (__expf rel err ~1e-6)
__device__ __forceinline__ float sigf(float x) {
    return __fdividef(1.0f, 1.0f + __expf(-x));
}
__device__ __forceinline__ float tanhf_(float x) {
    return __fdividef(2.0f, 1.0f + __expf(-2.0f * x)) - 1.0f;
}

extern __shared__ float sm[];

__global__ __launch_bounds__(256, 1)
void lstm_bidir_kernel(const float* __restrict__ x,
                       const float* __restrict__ Wih_f,
                       const float* __restrict__ Whh_f,
                       const float* __restrict__ bih_f,
                       const float* __restrict__ bhh_f,
                       const float* __restrict__ Wih_b,
                       const float* __restrict__ Whh_b,
                       const float* __restrict__ bih_b,
                       const float* __restrict__ bhh_b,
                       float* __restrict__ out)
{
    float* wsm = sm;             // [c(96)][j(256)]  (c: 0..31 input, 32..95 hidden)
    float* gsm = sm + GSM_OFF;   // [j(256)][nb(32)] stride 33 (padded)
    float* zsm = sm + ZSM_OFF;   // [row(96)][nb(32)] rows 0..31 x_t, 32..95 h

    const int tid = threadIdx.x;        // gate row j in [0,256)
    const int bid = blockIdx.x;         // 0..255
    const int dir = bid >> 7;           // 0 = forward, 1 = backward
    const int b7  = bid & 127;
    const int s   = b7 >> 2;            // sample
    const int a0  = (b7 & 3) * NB;      // asset tile base

    const float* Wih = dir ? Wih_b : Wih_f;
    const float* Whh = dir ? Whh_b : Whh_f;
    const float* bih = dir ? bih_b : bih_f;
    const float* bhh = dir ? bhh_b : bhh_f;

    // ---- Load weights transposed into smem: wsm[c*256 + j] ----
    // Wih: (256, 32) row-major (j, c)
    for (int idx = tid; idx < 256 * 32; idx += 256) {
        int j = idx >> 5, c = idx & 31;
        wsm[c * 256 + j] = Wih[idx];
    }
    // Whh: (256, 64) row-major (j, k) -> rows 32..95
    for (int idx = tid; idx < 256 * 64; idx += 256) {
        int j = idx >> 6, k = idx & 63;
        wsm[(32 + k) * 256 + j] = Whh[idx];
    }
    // zero the h rows of the operand tile
    for (int idx = tid; idx < 64 * 32; idx += 256) zsm[32 * 32 + idx] = 0.0f;

    const float bias = bih[tid] + bhh[tid];
    const unsigned long long bb = pack2(bias);

    // Update-phase identity: this thread owns sequence nb_u, hidden units k = wq + 8r
    const int nb_u = tid & 31;
    const int wq   = tid >> 5;

    float cst[8];
#pragma unroll
    for (int r = 0; r < 8; ++r) cst[r] = 0.0f;

    // Prologue: load x for the first timestep into zsm rows 0..31
    {
        const int tt0 = dir ? (T_LEN - 1) : 0;
        const float* xb = x + (((size_t)s * C_IN) * T_LEN + tt0) * A_N + a0;
#pragma unroll
        for (int q = 0; q < 4; ++q) {
            int c = q * 8 + wq;
            zsm[c * 32 + nb_u] = xb[(size_t)c * T_LEN * A_N + nb_u];
        }
    }
    __syncthreads();

    // out[s][dir*64 + k][t][a0 + nb_u]
    const size_t outBase0 =
        (((size_t)s * 128 + (dir ? H_DIR : 0)) * T_LEN) * A_N + a0 + nb_u;

    unsigned long long acc[16];

    for (int t = 0; t < T_LEN; ++t) {
        const int tt = dir ? (T_LEN - 1 - t) : t;

        // ---- Gate GEMV: g[nb][j] = b[j] + sum_c W[j][c] * z[nb][c] ----
#pragma unroll
        for (int p = 0; p < 16; ++p) acc[p] = bb;

#pragma unroll 4
        for (int c = 0; c < ZROWS; ++c) {
            unsigned long long w2 = pack2(wsm[c * 256 + tid]);   // {w, w}
            const ulonglong2* zr = (const ulonglong2*)(zsm + c * 32);
#pragma unroll
            for (int pp = 0; pp < 8; ++pp) {
                ulonglong2 v = zr[pp];   // pairs (nb=4pp,4pp+1) and (4pp+2,4pp+3)
                fma2(acc[2 * pp],     w2, v.x);
                fma2(acc[2 * pp + 1], w2, v.y);
            }
        }

        // Stash gates: gsm[j][nb], padded stride (conflict-free across the warp)
        {
            float* grow = gsm + tid * GSM_STRIDE;
#pragma unroll
            for (int p = 0; p < 16; ++p) {
                float2 f = unpack2(acc[p]);
                grow[2 * p]     = f.x;
                grow[2 * p + 1] = f.y;
            }
        }
        __syncthreads();

        // ---- State update + output + x prefetch for next step ----
        // issue LDGs for next x first so their latency overlaps the MUFU work
        const int ttn = dir ? (tt > 0 ? tt - 1 : 0)
                            : (tt < T_LEN - 1 ? tt + 1 : tt);
        float xpre[4];
        {
            const float* xb = x + (((size_t)s * C_IN) * T_LEN + ttn) * A_N + a0;
#pragma unroll
            for (int q = 0; q < 4; ++q) {
                int c = q * 8 + wq;
                xpre[q] = xb[(size_t)c * T_LEN * A_N + nb_u];
            }
        }

#pragma unroll
        for (int r = 0; r < 8; ++r) {
            const int k = wq + 8 * r;
            float gi = gsm[(k)*GSM_STRIDE + nb_u];
            float gf = gsm[(64 + k) * GSM_STRIDE + nb_u];
            float gg = gsm[(128 + k) * GSM_STRIDE + nb_u];
            float go = gsm[(192 + k) * GSM_STRIDE + nb_u];
            float cv = sigf(gf) * cst[r] + sigf(gi) * tanhf_(gg);
            cst[r] = cv;
            float h = sigf(go) * tanhf_(cv);
            zsm[(32 + k) * 32 + nb_u] = h;                     // feed next step
            out[outBase0 + (size_t)k * T_LEN * A_N + (size_t)tt * A_N] = h;
        }

        // write the prefetched x for the next step (x rows only read in gate phase)
#pragma unroll
        for (int q = 0; q < 4; ++q)
            zsm[(q * 8 + wq) * 32 + nb_u] = xpre[q];

        __syncthreads();
    }
}

extern "C" void kernel_launch(void* const* d_in, const int* in_sizes, int n_in,
                              void* d_out, int out_size)
{
    (void)in_sizes; (void)n_in; (void)out_size;
    const float* x     = (const float*)d_in[0];
    const float* Wih_f = (const float*)d_in[1];
    const float* Whh_f = (const float*)d_in[2];
    const float* bih_f = (const float*)d_in[3];
    const float* bhh_f = (const float*)d_in[4];
    const float* Wih_b = (const float*)d_in[5];
    const float* Whh_b = (const float*)d_in[6];
    const float* bih_b = (const float*)d_in[7];
    const float* bhh_b = (const float*)d_in[8];
    float* out = (float*)d_out;

    cudaFuncSetAttribute(lstm_bidir_kernel,
                         cudaFuncAttributeMaxDynamicSharedMemorySize, SMEM_BYTES);

    // 256 CTAs: [0,128) forward, [128,256) backward; each owns (s, 32-asset tile)
    lstm_bidir_kernel<<<256, 256, SMEM_BYTES>>>(
        x, Wih_f, Whh_f, bih_f, bhh_f, Wih_b, Whh_b, bih_b, bhh_b, out);
}

// round 10
// speedup vs baseline: 1.0007x; 1.0007x over previous
#include <cuda_runtime.h>
#include <cstdint>

// Problem constants
#define T_LEN 256
#define S_N   32
#define C_IN  32
#define A_N   128
#define H_DIR 64
#define G4    256      // 4*H_DIR gate rows
#define NB    32       // sequences (assets) per CTA
#define ZROWS 96       // C_IN + H_DIR rows of the per-step operand tile

// Shared memory layout (in floats)
#define WSM_SZ (96 * 256)          // transposed weights: wsm[c*256 + j]
#define GSM_STRIDE 33              // padded row stride for gate exchange
#define GSM_SZ (256 * GSM_STRIDE)  // gsm[j*33 + nb]
#define ZSM_SZ (96 * 32)           // zsm[row*32 + nb]; rows 0..31 = x_t, 32..95 = h
#define GSM_OFF WSM_SZ
#define ZSM_OFF (WSM_SZ + GSM_SZ)
#define SMEM_FLOATS (WSM_SZ + GSM_SZ + ZSM_SZ)
#define SMEM_BYTES (SMEM_FLOATS * 4)

// ---- packed fp32x2 helpers (Blackwell FFMA2: only reachable via PTX) ----
__device__ __forceinline__ unsigned long long pack2(float w) {
    unsigned long long r;
    unsigned int u = __float_as_uint(w);
    asm("mov.b64 %0, {%1, %1};" : "=l"(r) : "r"(u));
    return r;
}
__device__ __forceinline__ void fma2(unsigned long long& d,
                                     unsigned long long a,
                                     unsigned long long b) {
    asm("fma.rn.f32x2 %0, %1, %2, %0;" : "+l"(d) : "l"(a), "l"(b));
}
__device__ __forceinline__ float2 unpack2(unsigned long long v) {
    unsigned int lo, hi;
    asm("mov.b64 {%0, %1}, %2;" : "=r"(lo), "=r"(hi) : "l"(v));
    return make_float2(__uint_as_float(lo), __uint_as_float(hi));
}

// Fast, accurate-enough nonlinearities (__expf rel err ~1e-6)
__device__ __forceinline__ float sigf(float x) {
    return __fdividef(1.0f, 1.0f + __expf(-x));
}
__device__ __forceinline__ float tanhf_(float x) {
    return __fdividef(2.0f, 1.0f + __expf(-2.0f * x)) - 1.0f;
}

extern __shared__ float sm[];

__global__ __launch_bounds__(256, 1)
void lstm_bidir_kernel(const float* __restrict__ x,
                       const float* __restrict__ Wih_f,
                       const float* __restrict__ Whh_f,
                       const float* __restrict__ bih_f,
                       const float* __restrict__ bhh_f,
                       const float* __restrict__ Wih_b,
                       const float* __restrict__ Whh_b,
                       const float* __restrict__ bih_b,
                       const float* __restrict__ bhh_b,
                       float* __restrict__ out)
{
    float* wsm = sm;             // [c(96)][j(256)]  (c: 0..31 input, 32..95 hidden)
    float* gsm = sm + GSM_OFF;   // [j(256)][nb(32)] stride 33 (padded)
    float* zsm = sm + ZSM_OFF;   // [row(96)][nb(32)] rows 0..31 x_t, 32..95 h

    const int tid = threadIdx.x;        // gate row j in [0,256)
    const int bid = blockIdx.x;         // 0..255
    const int dir = bid >> 7;           // 0 = forward, 1 = backward
    const int b7  = bid & 127;
    const int s   = b7 >> 2;            // sample
    const int a0  = (b7 & 3) * NB;      // asset tile base

    const float* Wih = dir ? Wih_b : Wih_f;
    const float* Whh = dir ? Whh_b : Whh_f;
    const float* bih = dir ? bih_b : bih_f;
    const float* bhh = dir ? bhh_b : bhh_f;

    // ---- Load weights transposed into smem: wsm[c*256 + j] ----
    // Wih: (256, 32) row-major (j, c)
    for (int idx = tid; idx < 256 * 32; idx += 256) {
        int j = idx >> 5, c = idx & 31;
        wsm[c * 256 + j] = Wih[idx];
    }
    // Whh: (256, 64) row-major (j, k) -> rows 32..95
    for (int idx = tid; idx < 256 * 64; idx += 256) {
        int j = idx >> 6, k = idx & 63;
        wsm[(32 + k) * 256 + j] = Whh[idx];
    }
    // zero the h rows of the operand tile
    for (int idx = tid; idx < 64 * 32; idx += 256) zsm[32 * 32 + idx] = 0.0f;

    const float bias = bih[tid] + bhh[tid];
    const unsigned long long bb = pack2(bias);

    // Update-phase identity: this thread owns sequence nb_u, hidden units k = wq + 8r
    const int nb_u = tid & 31;
    const int wq   = tid >> 5;

    float cst[8];
#pragma unroll
    for (int r = 0; r < 8; ++r) cst[r] = 0.0f;

    // Prologue: load x for the first timestep into zsm rows 0..31
    {
        const int tt0 = dir ? (T_LEN - 1) : 0;
        const float* xb = x + (((size_t)s * C_IN) * T_LEN + tt0) * A_N + a0;
#pragma unroll
        for (int q = 0; q < 4; ++q) {
            int c = q * 8 + wq;
            zsm[c * 32 + nb_u] = xb[(size_t)c * T_LEN * A_N + nb_u];
        }
    }
    __syncthreads();

    // out[s][dir*64 + k][t][a0 + nb_u]
    const size_t outBase0 =
        (((size_t)s * 128 + (dir ? H_DIR : 0)) * T_LEN) * A_N + a0 + nb_u;

    unsigned long long acc[16];

    for (int t = 0; t < T_LEN; ++t) {
        const int tt = dir ? (T_LEN - 1 - t) : t;

        // ---- Gate GEMV: g[nb][j] = b[j] + sum_c W[j][c] * z[nb][c] ----
#pragma unroll
        for (int p = 0; p < 16; ++p) acc[p] = bb;

#pragma unroll 4
        for (int c = 0; c < ZROWS; ++c) {
            unsigned long long w2 = pack2(wsm[c * 256 + tid]);   // {w, w}
            const ulonglong2* zr = (const ulonglong2*)(zsm + c * 32);
#pragma unroll
            for (int pp = 0; pp < 8; ++pp) {
                ulonglong2 v = zr[pp];   // pairs (nb=4pp,4pp+1) and (4pp+2,4pp+3)
                fma2(acc[2 * pp],     w2, v.x);
                fma2(acc[2 * pp + 1], w2, v.y);
            }
        }

        // Stash gates: gsm[j][nb], padded stride (conflict-free across the warp)
        {
            float* grow = gsm + tid * GSM_STRIDE;
#pragma unroll
            for (int p = 0; p < 16; ++p) {
                float2 f = unpack2(acc[p]);
                grow[2 * p]     = f.x;
                grow[2 * p + 1] = f.y;
            }
        }
        __syncthreads();

        // ---- State update + output + x prefetch for next step ----
        // issue LDGs for next x first so their latency overlaps the MUFU work
        const int ttn = dir ? (tt > 0 ? tt - 1 : 0)
                            : (tt < T_LEN - 1 ? tt + 1 : tt);
        float xpre[4];
        {
            const float* xb = x + (((size_t)s * C_IN) * T_LEN + ttn) * A_N + a0;
#pragma unroll
            for (int q = 0; q < 4; ++q) {
                int c = q * 8 + wq;
                xpre[q] = xb[(size_t)c * T_LEN * A_N + nb_u];
            }
        }

#pragma unroll
        for (int r = 0; r < 8; ++r) {
            const int k = wq + 8 * r;
            float gi = gsm[(k)*GSM_STRIDE + nb_u];
            float gf = gsm[(64 + k) * GSM_STRIDE + nb_u];
            float gg = gsm[(128 + k) * GSM_STRIDE + nb_u];
            float go = gsm[(192 + k) * GSM_STRIDE + nb_u];
            float cv = sigf(gf) * cst[r] + sigf(gi) * tanhf_(gg);
            cst[r] = cv;
            float h = sigf(go) * tanhf_(cv);
            zsm[(32 + k) * 32 + nb_u] = h;                     // feed next step
            out[outBase0 + (size_t)k * T_LEN * A_N + (size_t)tt * A_N] = h;
        }

        // write the prefetched x for the next step (x rows only read in gate phase)
#pragma unroll
        for (int q = 0; q < 4; ++q)
            zsm[(q * 8 + wq) * 32 + nb_u] = xpre[q];

        __syncthreads();
    }
}

extern "C" void kernel_launch(void* const* d_in, const int* in_sizes, int n_in,
                              void* d_out, int out_size)
{
    (void)in_sizes; (void)n_in; (void)out_size;
    const float* x     = (const float*)d_in[0];
    const float* Wih_f = (const float*)d_in[1];
    const float* Whh_f = (const float*)d_in[2];
    const float* bih_f = (const float*)d_in[3];
    const float* bhh_f = (const float*)d_in[4];
    const float* Wih_b = (const float*)d_in[5];
    const float* Whh_b = (const float*)d_in[6];
    const float* bih_b = (const float*)d_in[7];
    const float* bhh_b = (const float*)d_in[8];
    float* out = (float*)d_out;

    cudaFuncSetAttribute(lstm_bidir_kernel,
                         cudaFuncAttributeMaxDynamicSharedMemorySize, SMEM_BYTES);

    // 256 CTAs: [0,128) forward, [128,256) backward; each owns (s, 32-asset tile)
    lstm_bidir_kernel<<<256, 256, SMEM_BYTES>>>(
        x, Wih_f, Whh_f, bih_f, bhh_f, Wih_b, Whh_b, bih_b, bhh_b, out);
}